// round 10
// baseline (speedup 1.0000x reference)
#include <cuda_runtime.h>
#include <cuda_fp16.h>
#include <cstdint>
#include <cstddef>

// Problem constants
#define NB   64
#define NS   512
#define NUNI 1024
#define NH   1024
#define NFLD 256
#define ROWS (NB * NS)                       // 32768
#define EMIT_ELEMS ((size_t)NB * NS * NH)    // 33554432

// ---------------- scratch (static __device__: no allocation) ----------------
__device__ float  g_pre[(size_t)ROWS * 4 * NH];   // (t*64+b) x 4096
__device__ float  g_ft [(size_t)ROWS * NH];       // (t*64+b) x 1024
__device__ __half g_hb16[2][NB * NH];             // fp16 h exchange buffers
__device__ unsigned g_flags[128 * 32];            // per-block step flags (128B apart)

// ---------------- helpers ----------------
__device__ __forceinline__ uint32_t f2tf32(float x) {
    uint32_t r;
    asm("cvt.rna.tf32.f32 %0, %1;" : "=r"(r) : "f"(x));
    return r;
}
__device__ __forceinline__ float tf32f(float x) { return __uint_as_float(f2tf32(x)); }

__device__ __forceinline__ void mma_tf32(float d[4], const uint32_t a[4], const uint32_t b[2]) {
    asm volatile(
        "mma.sync.aligned.m16n8k8.row.col.f32.tf32.tf32.f32 "
        "{%0,%1,%2,%3}, {%4,%5,%6,%7}, {%8,%9}, {%0,%1,%2,%3};"
        : "+f"(d[0]), "+f"(d[1]), "+f"(d[2]), "+f"(d[3])
        : "r"(a[0]), "r"(a[1]), "r"(a[2]), "r"(a[3]), "r"(b[0]), "r"(b[1]));
}

__device__ __forceinline__ void mma_f16(float d[4], uint32_t a0, uint32_t a1,
                                        uint32_t a2, uint32_t a3,
                                        uint32_t b0, uint32_t b1) {
    asm volatile(
        "mma.sync.aligned.m16n8k16.row.col.f32.f16.f16.f32 "
        "{%0,%1,%2,%3}, {%4,%5,%6,%7}, {%8,%9}, {%0,%1,%2,%3};"
        : "+f"(d[0]), "+f"(d[1]), "+f"(d[2]), "+f"(d[3])
        : "r"(a0), "r"(a1), "r"(a2), "r"(a3), "r"(b0), "r"(b1));
}

__device__ __forceinline__ uint32_t smem_u32(const void* p) {
    return (uint32_t)__cvta_generic_to_shared(p);
}
__device__ __forceinline__ uint32_t h2u(__half2 h) { return *(uint32_t*)&h; }

__device__ __forceinline__ float sigf(float x) { return 1.0f / (1.0f + expf(-x)); }

// ---------------- init: zero fp16 h buffer + flags ----------------
__global__ void init_kernel() {
    int i = blockIdx.x * blockDim.x + threadIdx.x;
    if (i < 128 * 32) g_flags[i] = 0u;
    if (i < NB * NH / 2) ((uint32_t*)g_hb16[0])[i] = 0u;
}

// =======================================================================
// fp16 double-buffered GEMM: C = A(MxK fp32)*B(KxN fp32) + bias, fp32 out
// BM=128, BN=128, BK=32, 256 threads (8 warps 4x2), warp tile 32x64.
// Output rows permuted: r=(b*512+t) -> (t*64+b).
// =======================================================================
#define BM 128
#define BN 128
#define BK 32
#define A16_STR 40          // halves per A row (32 + 8 pad)
#define B16_STR 136         // half2 per B k-pair row (128 + 8 pad)
#define A16_BUF (BM * A16_STR)      // 5120 halves
#define B16_BUF (16 * B16_STR)      // 2176 half2
#define GEMM16_SMEM (2 * A16_BUF * 2 + 2 * B16_BUF * 4)   // 37888 B

__global__ __launch_bounds__(256) void gemm_f16_db(
    const float* __restrict__ A, const float* __restrict__ B,
    const float* __restrict__ bias, float* __restrict__ C,
    int K, int lda, int ldb, int ldc)
{
    extern __shared__ char smraw[];
    __half*  As = (__half*)smraw;                       // 2 x 128 x 40 halves
    __half2* Bs = (__half2*)(smraw + 2 * A16_BUF * 2);  // 2 x 16 x 136 half2

    const int tid  = threadIdx.x;
    const int warp = tid >> 5, lane = tid & 31;
    const int wm = warp >> 1, wn = warp & 1;
    const int gid = lane >> 2, kid = lane & 3;
    const int m0 = blockIdx.y * BM;
    const int n0 = blockIdx.x * BN;

    float acc[2][8][4];
    #pragma unroll
    for (int i = 0; i < 2; i++)
        #pragma unroll
        for (int j = 0; j < 8; j++)
            #pragma unroll
            for (int q = 0; q < 4; q++) acc[i][j][q] = 0.0f;

    float4 ar[4], br0[2], br1[2];

    auto load_tile = [&](int kt) {
        #pragma unroll
        for (int i = 0; i < 4; i++) {
            int idx = tid + i * 256;
            int r = idx >> 3, q = idx & 7;
            ar[i] = *(const float4*)(A + (size_t)(m0 + r) * lda + kt + q * 4);
        }
        #pragma unroll
        for (int i = 0; i < 2; i++) {
            int s = tid + i * 256;
            int k2 = s >> 5, cg = s & 31;
            br0[i] = *(const float4*)(B + (size_t)(kt + 2 * k2)     * ldb + n0 + cg * 4);
            br1[i] = *(const float4*)(B + (size_t)(kt + 2 * k2 + 1) * ldb + n0 + cg * 4);
        }
    };
    auto store_tile = [&](int buf) {
        #pragma unroll
        for (int i = 0; i < 4; i++) {
            int idx = tid + i * 256;
            int r = idx >> 3, q = idx & 7;
            uint2 u;
            u.x = h2u(__floats2half2_rn(ar[i].x, ar[i].y));
            u.y = h2u(__floats2half2_rn(ar[i].z, ar[i].w));
            *(uint2*)&As[(size_t)buf * A16_BUF + r * A16_STR + q * 4] = u;
        }
        #pragma unroll
        for (int i = 0; i < 2; i++) {
            int s = tid + i * 256;
            int k2 = s >> 5, cg = s & 31;
            uint4 u;
            u.x = h2u(__floats2half2_rn(br0[i].x, br1[i].x));
            u.y = h2u(__floats2half2_rn(br0[i].y, br1[i].y));
            u.z = h2u(__floats2half2_rn(br0[i].z, br1[i].z));
            u.w = h2u(__floats2half2_rn(br0[i].w, br1[i].w));
            *(uint4*)&Bs[(size_t)buf * B16_BUF + k2 * B16_STR + cg * 4] = u;
        }
    };

    load_tile(0);
    store_tile(0);
    __syncthreads();

    for (int kt = 0; kt < K; kt += BK) {
        const int buf = (kt >> 5) & 1;
        const bool more = (kt + BK) < K;
        if (more) load_tile(kt + BK);

        const __half*  Ac = As + (size_t)buf * A16_BUF;
        const __half2* Bc = Bs + (size_t)buf * B16_BUF;
        #pragma unroll
        for (int kk2 = 0; kk2 < 2; kk2++) {
            uint32_t af[2][4], bf[8][2];
            #pragma unroll
            for (int mi = 0; mi < 2; mi++) {
                int r = wm * 32 + mi * 16 + gid;
                af[mi][0] = *(const uint32_t*)&Ac[r * A16_STR + kk2 * 16 + kid * 2];
                af[mi][1] = *(const uint32_t*)&Ac[(r + 8) * A16_STR + kk2 * 16 + kid * 2];
                af[mi][2] = *(const uint32_t*)&Ac[r * A16_STR + kk2 * 16 + kid * 2 + 8];
                af[mi][3] = *(const uint32_t*)&Ac[(r + 8) * A16_STR + kk2 * 16 + kid * 2 + 8];
            }
            #pragma unroll
            for (int ni = 0; ni < 8; ni++) {
                int cc = wn * 64 + ni * 8 + gid;
                bf[ni][0] = *(const uint32_t*)&Bc[(kk2 * 8 + kid)     * B16_STR + cc];
                bf[ni][1] = *(const uint32_t*)&Bc[(kk2 * 8 + kid + 4) * B16_STR + cc];
            }
            #pragma unroll
            for (int mi = 0; mi < 2; mi++)
                #pragma unroll
                for (int ni = 0; ni < 8; ni++)
                    mma_f16(acc[mi][ni], af[mi][0], af[mi][1], af[mi][2], af[mi][3],
                            bf[ni][0], bf[ni][1]);
        }
        if (more) store_tile(buf ^ 1);
        __syncthreads();
    }

    // Epilogue: bias + permuted store  (row b*512+t -> t*64+b)
    #pragma unroll
    for (int mi = 0; mi < 2; mi++) {
        int r = m0 + wm * 32 + mi * 16 + gid;
        int r0 = (r & (NS - 1)) * NB + (r >> 9);
        int r1 = ((r + 8) & (NS - 1)) * NB + ((r + 8) >> 9);
        #pragma unroll
        for (int ni = 0; ni < 8; ni++) {
            int cc = n0 + wn * 64 + ni * 8 + 2 * kid;
            float b0 = bias[cc], b1 = bias[cc + 1];
            C[(size_t)r0 * ldc + cc]     = acc[mi][ni][0] + b0;
            C[(size_t)r0 * ldc + cc + 1] = acc[mi][ni][1] + b1;
            C[(size_t)r1 * ldc + cc]     = acc[mi][ni][2] + b0;
            C[(size_t)r1 * ldc + cc + 1] = acc[mi][ni][3] + b1;
        }
    }
}

// =======================================================================
// fused field GEMM (tf32): ft = sig(F@W1r+br)*tanh(F@W1d+bd)
// =======================================================================
#define AS_STR 36
#define BS_STR 136
#define GEMM_SMEM ((2 * BM * AS_STR + 2 * BK * BS_STR) * 4)   // 71680 B

__device__ __forceinline__ void gemm_stage_store(
    float* As, float* Bs, int buf, const float4* ar, const float4* br, int tid)
{
    #pragma unroll
    for (int i = 0; i < 4; i++) {
        int idx = tid + i * 256;
        int r = idx >> 3, q = idx & 7;
        float4 v = ar[i];
        float4 cv = make_float4(tf32f(v.x), tf32f(v.y), tf32f(v.z), tf32f(v.w));
        *(float4*)&As[(size_t)buf * BM * AS_STR + r * AS_STR + q * 4] = cv;
    }
    #pragma unroll
    for (int i = 0; i < 4; i++) {
        int idx = tid + i * 256;
        int r = idx >> 5, q = idx & 31;
        float4 v = br[i];
        float4 cv = make_float4(tf32f(v.x), tf32f(v.y), tf32f(v.z), tf32f(v.w));
        *(float4*)&Bs[(size_t)buf * BK * BS_STR + r * BS_STR + q * 4] = cv;
    }
}

__global__ __launch_bounds__(256) void gemm_field_fused(
    const float* __restrict__ A, const float* __restrict__ B,
    const float* __restrict__ bias, float* __restrict__ C)
{
    extern __shared__ float sm[];
    float* As = sm;
    float* Bs = sm + 2 * BM * AS_STR;
    float* Ds = sm;

    const int tid  = threadIdx.x;
    const int warp = tid >> 5, lane = tid & 31;
    const int wm = warp >> 1, wn = warp & 1;
    const int gid = lane >> 2, kid = lane & 3;
    const int m0 = blockIdx.y * BM;
    const int n0 = blockIdx.x * 64;
    const int K = NFLD, lda = NFLD, ldb = 2 * NH;

    float acc[2][8][4];
    #pragma unroll
    for (int i = 0; i < 2; i++)
        #pragma unroll
        for (int j = 0; j < 8; j++)
            #pragma unroll
            for (int q = 0; q < 4; q++) acc[i][j][q] = 0.0f;

    float4 ar[4], br[4];
    #pragma unroll
    for (int i = 0; i < 4; i++) {
        int idx = tid + i * 256;
        int r = idx >> 3, q = idx & 7;
        ar[i] = *(const float4*)(A + (size_t)(m0 + r) * lda + q * 4);
    }
    #pragma unroll
    for (int i = 0; i < 4; i++) {
        int idx = tid + i * 256;
        int r = idx >> 5, q = idx & 31;
        int col = (q < 16) ? (n0 + q * 4) : (NH + n0 + (q - 16) * 4);
        br[i] = *(const float4*)(B + (size_t)r * ldb + col);
    }
    gemm_stage_store(As, Bs, 0, ar, br, tid);
    __syncthreads();

    for (int kt = 0; kt < K; kt += BK) {
        const int buf = (kt >> 5) & 1;
        const bool more = (kt + BK) < K;
        if (more) {
            #pragma unroll
            for (int i = 0; i < 4; i++) {
                int idx = tid + i * 256;
                int r = idx >> 3, q = idx & 7;
                ar[i] = *(const float4*)(A + (size_t)(m0 + r) * lda + kt + BK + q * 4);
            }
            #pragma unroll
            for (int i = 0; i < 4; i++) {
                int idx = tid + i * 256;
                int r = idx >> 5, q = idx & 31;
                int col = (q < 16) ? (n0 + q * 4) : (NH + n0 + (q - 16) * 4);
                br[i] = *(const float4*)(B + (size_t)(kt + BK + r) * ldb + col);
            }
        }
        const float* Ac = As + (size_t)buf * BM * AS_STR;
        const float* Bc = Bs + (size_t)buf * BK * BS_STR;
        #pragma unroll
        for (int kk = 0; kk < BK; kk += 8) {
            uint32_t af[2][4], bf[8][2];
            #pragma unroll
            for (int mi = 0; mi < 2; mi++) {
                int r = wm * 32 + mi * 16 + gid;
                af[mi][0] = __float_as_uint(Ac[r * AS_STR + kk + kid]);
                af[mi][1] = __float_as_uint(Ac[(r + 8) * AS_STR + kk + kid]);
                af[mi][2] = __float_as_uint(Ac[r * AS_STR + kk + kid + 4]);
                af[mi][3] = __float_as_uint(Ac[(r + 8) * AS_STR + kk + kid + 4]);
            }
            #pragma unroll
            for (int ni = 0; ni < 8; ni++) {
                int cc = wn * 64 + ni * 8 + gid;
                bf[ni][0] = __float_as_uint(Bc[(kk + kid) * BS_STR + cc]);
                bf[ni][1] = __float_as_uint(Bc[(kk + kid + 4) * BS_STR + cc]);
            }
            #pragma unroll
            for (int mi = 0; mi < 2; mi++)
                #pragma unroll
                for (int ni = 0; ni < 8; ni++)
                    mma_tf32(acc[mi][ni], af[mi], bf[ni]);
        }
        __syncthreads();
        if (more) { gemm_stage_store(As, Bs, buf ^ 1, ar, br, tid); __syncthreads(); }
    }

    if (wn == 1) {
        #pragma unroll
        for (int mi = 0; mi < 2; mi++) {
            int lr = wm * 32 + mi * 16 + gid;
            #pragma unroll
            for (int ni = 0; ni < 8; ni++) {
                int cc = ni * 8 + 2 * kid;
                float b0 = bias[NH + n0 + cc], b1 = bias[NH + n0 + cc + 1];
                Ds[lr * 68 + cc]           = acc[mi][ni][0] + b0;
                Ds[lr * 68 + cc + 1]       = acc[mi][ni][1] + b1;
                Ds[(lr + 8) * 68 + cc]     = acc[mi][ni][2] + b0;
                Ds[(lr + 8) * 68 + cc + 1] = acc[mi][ni][3] + b1;
            }
        }
    }
    __syncthreads();
    if (wn == 0) {
        #pragma unroll
        for (int mi = 0; mi < 2; mi++) {
            int lr = wm * 32 + mi * 16 + gid;
            int r = m0 + lr;
            int r0 = (r & (NS - 1)) * NB + (r >> 9);
            int r1 = ((r + 8) & (NS - 1)) * NB + ((r + 8) >> 9);
            #pragma unroll
            for (int ni = 0; ni < 8; ni++) {
                int cc = ni * 8 + 2 * kid;
                float b0 = bias[n0 + cc], b1 = bias[n0 + cc + 1];
                float2 o0, o1;
                o0.x = sigf(acc[mi][ni][0] + b0) * tanhf(Ds[lr * 68 + cc]);
                o0.y = sigf(acc[mi][ni][1] + b1) * tanhf(Ds[lr * 68 + cc + 1]);
                o1.x = sigf(acc[mi][ni][2] + b0) * tanhf(Ds[(lr + 8) * 68 + cc]);
                o1.y = sigf(acc[mi][ni][3] + b1) * tanhf(Ds[(lr + 8) * 68 + cc + 1]);
                *(float2*)(C + (size_t)r0 * NH + n0 + cc) = o0;
                *(float2*)(C + (size_t)r1 * NH + n0 + cc) = o1;
            }
        }
    }
}

// =======================================================================
// persistent fp16 LSTM recurrence — DATAFLOW version (no global barrier)
// 128 blocks x 256 threads. Block owns 8 h-cols (32 gate cols).
// Producer/consumer sync via per-block step flags: consumer thread with
// q = tid&15 loading chunk ci needs ONLY producer block 16*ci+q.
// Spin has nanosleep backoff after 64 iters (congestion hardening).
// =======================================================================
#define PBLK 128
#define KC 128
#define RS 136                                   // halves per staged A row
#define CHUNK_BYTES (64 * RS * 2)                // 17408
#define WHF_HALVES (8 * 8 * 2 * 32 * 8)          // 32768 halves = 64KB
#define PERS_SMEM (WHF_HALVES * 2 + 2 * CHUNK_BYTES)   // 100352 B

__global__ __launch_bounds__(256) void lstm_persistent(
    const float* __restrict__ W, const int* __restrict__ len, float* __restrict__ out)
{
    extern __shared__ __half smh[];
    __half* Whf   = smh;                          // fragment-ordered Wh
    __half* Asb16 = smh + WHF_HALVES;             // 2 x 64 x 136 halves
    float*  Gs    = (float*)Asb16;                // epilogue alias
    __shared__ int lens[NB];

    const int tid  = threadIdx.x;
    const int warp = tid >> 5, lane = tid & 31;
    const int wm = warp >> 1, wg = warp & 1;
    const int gid = lane >> 2, kid = lane & 3;
    const int bid = blockIdx.x;
    const int hbase = bid * 8;
    const float* Wh = W + (size_t)1024 * 4096;
    const uint4* Whf4 = (const uint4*)Whf;

    // ---- init: pack Wh fragments (fp16) ----
    for (int item = tid; item < 4096; item += 256) {
        int ln = item & 31, wgi = (item >> 5) & 1, g = (item >> 6) & 7, ci = item >> 9;
        int t4 = ln & 3, gi = ln >> 2;
        int kbase = ci * 128 + g * 16 + t4 * 2;
        __half hv[8];
        #pragma unroll
        for (int ni = 0; ni < 2; ni++) {
            int cc = wgi * 16 + ni * 8 + gi;
            int gcol = (cc >> 3) * 1024 + hbase + (cc & 7);
            hv[ni * 4 + 0] = __float2half(Wh[(size_t)(kbase + 0) * 4096 + gcol]);
            hv[ni * 4 + 1] = __float2half(Wh[(size_t)(kbase + 1) * 4096 + gcol]);
            hv[ni * 4 + 2] = __float2half(Wh[(size_t)(kbase + 8) * 4096 + gcol]);
            hv[ni * 4 + 3] = __float2half(Wh[(size_t)(kbase + 9) * 4096 + gcol]);
        }
        *(uint4*)&Whf[(size_t)item * 8] = *(uint4*)hv;
    }
    if (tid < NB) lens[tid] = len[tid];
    __syncthreads();

    const int eb  = tid >> 2;
    const int ehc = (tid & 3) * 2;
    const int mylen = lens[eb];
    const int hcol  = hbase + ehc;
    float2 creg = make_float2(0.f, 0.f);
    float2 hreg = make_float2(0.f, 0.f);

    const uint32_t asb = smem_u32(Asb16);
    const uint32_t aBase0 = asb + (((wm * 16 + (lane & 15)) * RS + (lane >> 4) * 8) * 2);

    // epilogue operand prefetch for t=0
    float2 pg0, pg1, pg2, pg3, ftv;
    {
        size_t prow = (size_t)0 * NB + eb;
        pg0 = *(const float2*)(g_pre + prow * 4096 +        hcol);
        pg1 = *(const float2*)(g_pre + prow * 4096 + 1024 + hcol);
        pg2 = *(const float2*)(g_pre + prow * 4096 + 2048 + hcol);
        pg3 = *(const float2*)(g_pre + prow * 4096 + 3072 + hcol);
        ftv = *(const float2*)(g_ft  + prow * 1024 +        hcol);
    }

    const int myq = tid & 15;   // this thread's cp.async column slot -> producer 16*ci+myq

    for (int t = 0; t < NS; t++) {
        const __half* hr16 = g_hb16[t & 1];
        __half*       hw16 = g_hb16[(t & 1) ^ 1];

        float acc[2][4] = {{0.f,0.f,0.f,0.f},{0.f,0.f,0.f,0.f}};

        // wait for this thread's producer of chunk ci, then issue 4 cp.async
        auto issue = [&](int ci) {
            // poll the single producer block whose 8 h-cols this thread loads
            unsigned v;
            int spins = 0;
            const unsigned* fp = g_flags + (ci * 16 + myq) * 32;
            while (true) {
                asm volatile("ld.acquire.gpu.u32 %0, [%1];" : "=r"(v) : "l"(fp) : "memory");
                if ((int)v >= t) break;
                if (++spins > 64) __nanosleep(100);
            }

            int kn = ci * KC, buf = ci & 1;
            #pragma unroll
            for (int j = 0; j < 4; j++) {
                int s = tid + j * 256;
                int row = s >> 4;
                uint32_t dst = asb + buf * CHUNK_BYTES + (row * RS + myq * 8) * 2;
                const __half* src = hr16 + (size_t)row * NH + kn + myq * 8;
                asm volatile("cp.async.cg.shared.global [%0], [%1], 16;"
                             :: "r"(dst), "l"(src));
            }
            asm volatile("cp.async.commit_group;");
        };

        issue(0);
        #pragma unroll 1
        for (int ci = 0; ci < 8; ci++) {
            if (ci < 7) {
                issue(ci + 1);
                asm volatile("cp.async.wait_group 1;");
            } else {
                asm volatile("cp.async.wait_group 0;");
            }
            __syncthreads();

            const uint32_t aB = aBase0 + (ci & 1) * CHUNK_BYTES;
            #pragma unroll
            for (int g = 0; g < 8; g++) {
                uint32_t a0, a1, a2, a3;
                asm volatile(
                    "ldmatrix.sync.aligned.m8n8.x4.shared.b16 {%0,%1,%2,%3}, [%4];"
                    : "=r"(a0), "=r"(a1), "=r"(a2), "=r"(a3)
                    : "r"(aB + g * 32));
                uint4 bv = Whf4[(((ci << 3) + g) * 2 + wg) * 32 + lane];
                mma_f16(acc[0], a0, a1, a2, a3, bv.x, bv.y);
                mma_f16(acc[1], a0, a1, a2, a3, bv.z, bv.w);
            }
            __syncthreads();
        }

        // gate exchange (Gs aliases A buffers — free after last sync)
        {
            int rr = wm * 16 + gid;
            #pragma unroll
            for (int ni = 0; ni < 2; ni++) {
                int cc = wg * 16 + ni * 8 + 2 * kid;
                Gs[rr * 36 + cc]           = acc[ni][0];
                Gs[rr * 36 + cc + 1]       = acc[ni][1];
                Gs[(rr + 8) * 36 + cc]     = acc[ni][2];
                Gs[(rr + 8) * 36 + cc + 1] = acc[ni][3];
            }
        }
        __syncthreads();

        // cell update (2 cells per thread)
        bool act = (t < mylen);
        float gi0 = Gs[eb * 36 + ehc]      + pg0.x;
        float gj0 = Gs[eb * 36 + 8 + ehc]  + pg1.x;
        float gf0 = Gs[eb * 36 + 16 + ehc] + pg2.x;
        float go0 = Gs[eb * 36 + 24 + ehc] + pg3.x;
        float gi1 = Gs[eb * 36 + ehc + 1]      + pg0.y;
        float gj1 = Gs[eb * 36 + 8 + ehc + 1]  + pg1.y;
        float gf1 = Gs[eb * 36 + 16 + ehc + 1] + pg2.y;
        float go1 = Gs[eb * 36 + 24 + ehc + 1] + pg3.y;

        float cn0 = sigf(gf0 + 1.0f) * creg.x + sigf(gi0) * tanhf(gj0) + ftv.x;
        float hn0 = sigf(go0) * tanhf(cn0);
        float cn1 = sigf(gf1 + 1.0f) * creg.y + sigf(gi1) * tanhf(gj1) + ftv.y;
        float hn1 = sigf(go1) * tanhf(cn1);

        float2 emit = make_float2(act ? hn0 : 0.0f, act ? hn1 : 0.0f);
        creg.x = act ? cn0 : creg.x;  creg.y = act ? cn1 : creg.y;
        hreg.x = act ? hn0 : hreg.x;  hreg.y = act ? hn1 : hreg.y;

        // publish h for step t+1, then flag
        *(__half2*)(hw16 + (size_t)eb * NH + hcol) = __floats2half2_rn(hreg.x, hreg.y);
        __threadfence();
        __syncthreads();

        if (t < NS - 1) {
            if (tid == 0) {
                asm volatile("st.release.gpu.u32 [%0], %1;"
                             :: "l"(g_flags + bid * 32), "r"((unsigned)(t + 1)) : "memory");
            }
            // off critical path: emit store + next-step operand prefetch
            *(float2*)(out + ((size_t)eb * NS + t) * NH + hcol) = emit;
            {
                size_t prow = (size_t)(t + 1) * NB + eb;
                pg0 = *(const float2*)(g_pre + prow * 4096 +        hcol);
                pg1 = *(const float2*)(g_pre + prow * 4096 + 1024 + hcol);
                pg2 = *(const float2*)(g_pre + prow * 4096 + 2048 + hcol);
                pg3 = *(const float2*)(g_pre + prow * 4096 + 3072 + hcol);
                ftv = *(const float2*)(g_ft  + prow * 1024 +        hcol);
            }
        } else {
            *(float2*)(out + ((size_t)eb * NS + t) * NH + hcol) = emit;
        }
    }

    // finals (fp32 from registers)
    *(float2*)(out + EMIT_ELEMS + (size_t)eb * NH + hcol)           = hreg;
    *(float2*)(out + EMIT_ELEMS + NB * NH + (size_t)eb * NH + hcol) = creg;
}

// ---------------- host ----------------
extern "C" void kernel_launch(void* const* d_in, const int* in_sizes, int n_in,
                              void* d_out, int out_size)
{
    const float* X   = (const float*)d_in[0];  // (64, 512, 1024)
    const float* F   = (const float*)d_in[1];  // (64, 512, 256)
    const int*   len = (const int*)  d_in[2];  // (64,)
    const float* W   = (const float*)d_in[3];  // (2048, 4096)
    const float* bW  = (const float*)d_in[4];  // (4096,)
    const float* W1  = (const float*)d_in[5];  // (256, 2048)
    const float* bW1 = (const float*)d_in[6];  // (2048,)
    float* out = (float*)d_out;

    float *pre_p, *ft_p;
    cudaGetSymbolAddress((void**)&pre_p, g_pre);
    cudaGetSymbolAddress((void**)&ft_p,  g_ft);

    // idempotent, no static guards
    cudaFuncSetAttribute(gemm_f16_db,
                         cudaFuncAttributeMaxDynamicSharedMemorySize, GEMM16_SMEM);
    cudaFuncSetAttribute(gemm_field_fused,
                         cudaFuncAttributeMaxDynamicSharedMemorySize, GEMM_SMEM);
    cudaFuncSetAttribute(lstm_persistent,
                         cudaFuncAttributeMaxDynamicSharedMemorySize, PERS_SMEM);

    // reset flags + zero fp16 h buffer
    init_kernel<<<256, 256>>>();

    // pre = X @ W[0:1024,:] + bW  -> permuted rows (t*64+b)   [fp16 tensor cores]
    gemm_f16_db<<<dim3(4 * NH / BN, ROWS / BM), 256, GEMM16_SMEM>>>(
        X, W, bW, pre_p, NUNI, NUNI, 4 * NH, 4 * NH);

    // ft = sigmoid(F@W1_r + b_r) * tanh(F@W1_d + b_d)  -> permuted rows (tf32)
    gemm_field_fused<<<dim3(16, ROWS / BM), 256, GEMM_SMEM>>>(F, W1, bW1, ft_p);

    // recurrence: one persistent dataflow kernel
    lstm_persistent<<<PBLK, 256, PERS_SMEM>>>(W, len, out);
}